// round 17
// baseline (speedup 1.0000x reference)
#include <cuda_runtime.h>

// TT-linear: y = x @ W^T + bias
//   c0: [1,32(o0),32(i0),4(r1)]  c1: [4(r1),16(o1),16(i1),4(r2)]  c2: [4(r2),16(o2),16(i2),1]
//
// K0: out = bias (broadcast fill).
// K1: relayout c1 -> g_c1s [o1][i1][zz][rr][r2], c0 -> g_c0s [i0][r1][o0]  (L1-resident).
// K2: grid 256 = (token-pair 64) x (i0-quarter 4); 256 thr; 2 CTAs/SM; ONE wave.
//   Lane map: o2 = tid&15, z = (tid>>4)&1, o1p = tid>>5 (warp-uniform).
//   4-deep sA/sX ring -> TWO slices per __syncthreads (6 syncs total, 2x independent
//   chains per interval). c1/c0 read via __ldg (off the smem crossbar).
//   step1: thread produces A row i1=2*o1p+z, both tokens, shared smem c2 loads.
//   step2: z splits r1-pairs, all 16 i1; partner exchange via shfl_xor(16).
//   step3: z splits o0. Epilogue: RED.ADD into bias-prefilled out.

#define THREADS 256

typedef unsigned long long u64;

__device__ float g_c1s[4096];   // [o1 16][i1 16][zz 2][rr 2][r2 4]
__device__ float g_c0s[4096];   // [i0 32][r1 4][o0 32]

__device__ __forceinline__ u64 pk2(float lo, float hi) {
    u64 r;
    asm("mov.b64 %0, {%1, %2};" : "=l"(r) : "f"(lo), "f"(hi));
    return r;
}
__device__ __forceinline__ void unpk(u64 v, float& lo, float& hi) {
    asm("mov.b64 {%0, %1}, %2;" : "=f"(lo), "=f"(hi) : "l"(v));
}
__device__ __forceinline__ u64 fma2(u64 a, u64 b, u64 c) {
    u64 d;
    asm("fma.rn.f32x2 %0, %1, %2, %3;" : "=l"(d) : "l"(a), "l"(b), "l"(c));
    return d;
}
__device__ __forceinline__ float hadd(u64 v) {
    float lo, hi;
    unpk(v, lo, hi);
    return lo + hi;
}

// step1: A_t[i1][o2][r2] for BOTH tokens, one i1 row, shared c2 loads. (R13/R16 verbatim)
__device__ __forceinline__ void step1_both(const float* __restrict__ Xs0,
                                           const float* __restrict__ Xs1,
                                           float* __restrict__ Ad0,
                                           float* __restrict__ Ad1,
                                           const float* __restrict__ sc2,
                                           int i1, int o2)
{
    u64 a01_0 = 0ull, a23_0 = 0ull, a01_1 = 0ull, a23_1 = 0ull;
    #pragma unroll
    for (int ch = 0; ch < 2; ch++) {
        const float4* xq0 = reinterpret_cast<const float4*>(&Xs0[i1 * 16 + ch * 8]);
        const float4* xq1 = reinterpret_cast<const float4*>(&Xs1[i1 * 16 + ch * 8]);
        float4 p0 = xq0[0], p1 = xq0[1];
        float4 q0 = xq1[0], q1 = xq1[1];
        float xs0[8] = { p0.x,p0.y,p0.z,p0.w, p1.x,p1.y,p1.z,p1.w };
        float xs1[8] = { q0.x,q0.y,q0.z,q0.w, q1.x,q1.y,q1.z,q1.w };
        #pragma unroll
        for (int j = 0; j < 8; j++) {
            const int i2 = ch * 8 + j;
            ulonglong2 c = *reinterpret_cast<const ulonglong2*>(&sc2[(i2 * 16 + o2) * 4]);
            u64 xd0 = pk2(xs0[j], xs0[j]);
            u64 xd1 = pk2(xs1[j], xs1[j]);
            a01_0 = fma2(xd0, c.x, a01_0);
            a23_0 = fma2(xd0, c.y, a23_0);
            a01_1 = fma2(xd1, c.x, a01_1);
            a23_1 = fma2(xd1, c.y, a23_1);
        }
    }
    ulonglong2 st0; st0.x = a01_0; st0.y = a23_0;
    ulonglong2 st1; st1.x = a01_1; st1.y = a23_1;
    *reinterpret_cast<ulonglong2*>(&Ad0[(i1 * 16 + o2) * 4]) = st0;
    *reinterpret_cast<ulonglong2*>(&Ad1[(i1 * 16 + o2) * 4]) = st1;
}

__global__ __launch_bounds__(THREADS, 2)
void tt_partial_kernel(const float* __restrict__ x,
                       const float* __restrict__ g2,
                       float* __restrict__ out)
{
    __shared__ __align__(16) float sc2[1024];       // [i2][o2][r2]
    __shared__ __align__(16) float sA[4][2][1024];  // ring: [buf][tok][i1][o2][r2]
    __shared__ __align__(16) float sX[4][2][256];   // ring: [buf][tok][elem]

    const int tid     = threadIdx.x;
    const int o2      = tid & 15;
    const int z       = (tid >> 4) & 1;
    const int o1p     = tid >> 5;                   // 0..7; warp-uniform
    const int pair    = blockIdx.x & 63;
    const int quarter = blockIdx.x >> 6;            // 0..3
    const int i0base  = quarter * 8;                // 8 slices per CTA

    for (int idx = tid; idx < 1024; idx += THREADS) {
        int r2 = idx & 3, o2g = (idx >> 2) & 15, i2 = idx >> 6;
        sc2[idx] = g2[(r2 * 16 + o2g) * 16 + i2];
    }

    const float* x0 = x + (2 * pair + 0) * 8192;
    const float* x1 = x + (2 * pair + 1) * 8192;

    // stage x slices 0..3
    #pragma unroll
    for (int s = 0; s < 4; s++) {
        sX[s][0][tid] = x0[(i0base + s) * 256 + tid];
        sX[s][1][tid] = x1[(i0base + s) * 256 + tid];
    }

    u64 yp[2][2][8];                      // [o1sel][tok][o0'-pair], own z o0-half
    #pragma unroll
    for (int a = 0; a < 2; a++)
        #pragma unroll
        for (int t = 0; t < 2; t++)
            #pragma unroll
            for (int i = 0; i < 8; i++) yp[a][t][i] = 0ull;

    const int i1prod = 2 * o1p + z;

    __syncthreads();

    // prologue: step1 for slices 0,1 into bufs 0,1
    step1_both(sX[0][0], sX[0][1], sA[0][0], sA[0][1], sc2, i1prod, o2);
    step1_both(sX[1][0], sX[1][1], sA[1][0], sA[1][1], sc2, i1prod, o2);
    __syncthreads();

    #pragma unroll
    for (int j = 0; j < 4; j++) {
        const int a = 2 * j;

        // stage x for slices a+4, a+5 into ring slots (a&3),(a+1)&3 — their old
        // contents (x of slices a, a+1) were last read before the previous sync.
        if (j < 2) {
            sX[a & 3][0][tid]       = x0[(i0base + a + 4) * 256 + tid];
            sX[a & 3][1][tid]       = x1[(i0base + a + 4) * 256 + tid];
            sX[(a + 1) & 3][0][tid] = x0[(i0base + a + 5) * 256 + tid];
            sX[(a + 1) & 3][1][tid] = x1[(i0base + a + 5) * 256 + tid];
        }

        // ---- step2+step3 for slices a and a+1 (independent chains) ----
        #pragma unroll
        for (int kk = 0; kk < 2; kk++) {
            const int k = a + kk;
            const int i0abs = i0base + k;
            const float* A0 = sA[k & 3][0];
            const float* A1 = sA[k & 3][1];

            u64 acc[2][2][2];             // [o1sel][tok][rr]
            #pragma unroll
            for (int aa = 0; aa < 2; aa++)
                #pragma unroll
                for (int t = 0; t < 2; t++) { acc[aa][t][0] = 0ull; acc[aa][t][1] = 0ull; }

            #pragma unroll
            for (int i1 = 0; i1 < 16; i1++) {
                const ulonglong2 av0 = *reinterpret_cast<const ulonglong2*>(
                    &A0[(i1 * 16 + o2) * 4]);
                const ulonglong2 av1 = *reinterpret_cast<const ulonglong2*>(
                    &A1[(i1 * 16 + o2) * 4]);
                const ulonglong2* cpA = reinterpret_cast<const ulonglong2*>(
                    &g_c1s[(o1p * 16 + i1) * 16 + z * 8]);
                const ulonglong2* cpB = reinterpret_cast<const ulonglong2*>(
                    &g_c1s[((o1p + 8) * 16 + i1) * 16 + z * 8]);
                ulonglong2 cA0 = __ldg(cpA);       // rr=0
                ulonglong2 cA1 = __ldg(cpA + 1);   // rr=1
                ulonglong2 cB0 = __ldg(cpB);
                ulonglong2 cB1 = __ldg(cpB + 1);
                acc[0][0][0] = fma2(av0.x, cA0.x, acc[0][0][0]);
                acc[0][0][0] = fma2(av0.y, cA0.y, acc[0][0][0]);
                acc[0][0][1] = fma2(av0.x, cA1.x, acc[0][0][1]);
                acc[0][0][1] = fma2(av0.y, cA1.y, acc[0][0][1]);
                acc[0][1][0] = fma2(av1.x, cA0.x, acc[0][1][0]);
                acc[0][1][0] = fma2(av1.y, cA0.y, acc[0][1][0]);
                acc[0][1][1] = fma2(av1.x, cA1.x, acc[0][1][1]);
                acc[0][1][1] = fma2(av1.y, cA1.y, acc[0][1][1]);
                acc[1][0][0] = fma2(av0.x, cB0.x, acc[1][0][0]);
                acc[1][0][0] = fma2(av0.y, cB0.y, acc[1][0][0]);
                acc[1][0][1] = fma2(av0.x, cB1.x, acc[1][0][1]);
                acc[1][0][1] = fma2(av0.y, cB1.y, acc[1][0][1]);
                acc[1][1][0] = fma2(av1.x, cB0.x, acc[1][1][0]);
                acc[1][1][0] = fma2(av1.y, cB0.y, acc[1][1][0]);
                acc[1][1][1] = fma2(av1.x, cB1.x, acc[1][1][1]);
                acc[1][1][1] = fma2(av1.y, cB1.y, acc[1][1][1]);
            }

            // own r1-pair -> scalars; partner's via shfl_xor(16); bd[4]
            u64 bd[2][2][4];
            #pragma unroll
            for (int aa = 0; aa < 2; aa++)
                #pragma unroll
                for (int t = 0; t < 2; t++) {
                    float p0 = hadd(acc[aa][t][0]);
                    float p1 = hadd(acc[aa][t][1]);
                    float q0 = __shfl_xor_sync(0xffffffffu, p0, 16);
                    float q1 = __shfl_xor_sync(0xffffffffu, p1, 16);
                    float s0 = z ? q0 : p0;
                    float s1 = z ? q1 : p1;
                    float s2 = z ? p0 : q0;
                    float s3 = z ? p1 : q1;
                    bd[aa][t][0] = pk2(s0, s0);
                    bd[aa][t][1] = pk2(s1, s1);
                    bd[aa][t][2] = pk2(s2, s2);
                    bd[aa][t][3] = pk2(s3, s3);
                }

            // step3: own z o0-half; c0 via __ldg broadcast
            #pragma unroll
            for (int r1 = 0; r1 < 4; r1++) {
                const ulonglong2* cq = reinterpret_cast<const ulonglong2*>(
                    &g_c0s[i0abs * 128 + r1 * 32 + z * 16]);
                #pragma unroll
                for (int q = 0; q < 4; q++) {
                    ulonglong2 c = __ldg(cq + q);
                    yp[0][0][2 * q]     = fma2(bd[0][0][r1], c.x, yp[0][0][2 * q]);
                    yp[0][0][2 * q + 1] = fma2(bd[0][0][r1], c.y, yp[0][0][2 * q + 1]);
                    yp[0][1][2 * q]     = fma2(bd[0][1][r1], c.x, yp[0][1][2 * q]);
                    yp[0][1][2 * q + 1] = fma2(bd[0][1][r1], c.y, yp[0][1][2 * q + 1]);
                    yp[1][0][2 * q]     = fma2(bd[1][0][r1], c.x, yp[1][0][2 * q]);
                    yp[1][0][2 * q + 1] = fma2(bd[1][0][r1], c.y, yp[1][0][2 * q + 1]);
                    yp[1][1][2 * q]     = fma2(bd[1][1][r1], c.x, yp[1][1][2 * q]);
                    yp[1][1][2 * q + 1] = fma2(bd[1][1][r1], c.y, yp[1][1][2 * q + 1]);
                }
            }
        }

        // ---- step1 for slices a+2, a+3 into ring slots (a+2)&3, (a+3)&3 ----
        if (j < 3) {
            step1_both(sX[(a + 2) & 3][0], sX[(a + 2) & 3][1],
                       sA[(a + 2) & 3][0], sA[(a + 2) & 3][1], sc2, i1prod, o2);
            step1_both(sX[(a + 3) & 3][0], sX[(a + 3) & 3][1],
                       sA[(a + 3) & 3][0], sA[(a + 3) & 3][1], sc2, i1prod, o2);
        }
        __syncthreads();
    }

    // ---- epilogue: RED.ADD into bias-prefilled out ----
    #pragma unroll
    for (int a = 0; a < 2; a++) {
        const int col = (o1p + 8 * a) * 16 + o2;
        #pragma unroll
        for (int t = 0; t < 2; t++) {
            float* ob = out + (size_t)(2 * pair + t) * 8192 + (z * 16) * 256 + col;
            #pragma unroll
            for (int q = 0; q < 4; q++) {
                float f0, f1, f2, f3;
                unpk(yp[a][t][2 * q],     f0, f1);
                unpk(yp[a][t][2 * q + 1], f2, f3);
                atomicAdd(ob + (4 * q + 0) * 256, f0);
                atomicAdd(ob + (4 * q + 1) * 256, f1);
                atomicAdd(ob + (4 * q + 2) * 256, f2);
                atomicAdd(ob + (4 * q + 3) * 256, f3);
            }
        }
    }
}

__global__ __launch_bounds__(256)
void tt_relayout_kernel(const float* __restrict__ g0, const float* __restrict__ g1)
{
    int idx = blockIdx.x * 256 + threadIdx.x;       // grid 32 -> 8192
    if (idx < 4096) {
        int r2 = idx & 3, rr = (idx >> 2) & 1, zz = (idx >> 3) & 1,
            i1 = (idx >> 4) & 15, o1 = idx >> 8;
        g_c1s[idx] = g1[(((2 * zz + rr) * 16 + o1) * 16 + i1) * 4 + r2];
    } else {
        int j = idx - 4096;
        int o0 = j & 31, r1 = (j >> 5) & 3, i0 = j >> 7;
        g_c0s[j] = g0[(o0 * 32 + i0) * 4 + r1];
    }
}

__global__ __launch_bounds__(128)
void tt_bias_kernel(const float* __restrict__ bias, float* __restrict__ out)
{
    // out = 262144 float4 = 128 copies of bias (2048 float4 each); grid 2048
    const int v = blockIdx.x * 128 + threadIdx.x;
    reinterpret_cast<float4*>(out)[v] =
        reinterpret_cast<const float4*>(bias)[v & 2047];
}

extern "C" void kernel_launch(void* const* d_in, const int* in_sizes, int n_in,
                              void* d_out, int out_size)
{
    const float* x    = (const float*)d_in[0];  // [128, 8192]
    const float* g0   = (const float*)d_in[1];  // [1,32,32,4]
    const float* g1   = (const float*)d_in[2];  // [4,16,16,4]
    const float* g2   = (const float*)d_in[3];  // [4,16,16,1]
    const float* bias = (const float*)d_in[4];  // [8192]
    float* out = (float*)d_out;                 // [128, 8192]

    tt_bias_kernel<<<2048, 128>>>(bias, out);
    tt_relayout_kernel<<<32, 256>>>(g0, g1);
    tt_partial_kernel<<<256, THREADS>>>(x, g2, out);
}